// round 15
// baseline (speedup 1.0000x reference)
#include <cuda_runtime.h>

// EDACLayer — R15 probe: full-plane blocks, 12-14 LDG.128 front batch/thread
// (the only unprobed direction on the MLP axis that has dominated all rounds).
//
// Shape (fixed): main (32,256,56,56) f32, dup (32,64,56,56) f32,
// min/max (256,), vidx (64,) i32, out (32,256,56,56) f32.
// lo <= 0 < hi by construction, inputs finite -> nan_to_num is a no-op
// for the final result (NaN/inf fail the range predicates either way).
#define BB 32
#define CC 256
#define HWSZ (56 * 56)       // 3136
#define HW4 (HWSZ / 4)       // 784 = 6*128 + 16 float4 per plane

__device__ __forceinline__ float edac_elem(float m, float d, float lo, float hi) {
    bool mv = (m >= lo) && (m <= hi);
    bool dv = (d >= lo) && (d <= hi);
    if (mv && dv) return fminf(m, d);   // m==d: fminf == m, same as ref
    if (dv) return d;
    return mv ? m : 0.0f;
}

__device__ __forceinline__ float clamp_elem(float m, float lo, float hi) {
    return ((m >= lo) && (m <= hi)) ? m : 0.0f;
}

__device__ __forceinline__ float4 edac4(float4 m, float4 d, float lo, float hi) {
    float4 r;
    r.x = edac_elem(m.x, d.x, lo, hi);
    r.y = edac_elem(m.y, d.y, lo, hi);
    r.z = edac_elem(m.z, d.z, lo, hi);
    r.w = edac_elem(m.w, d.w, lo, hi);
    return r;
}

__device__ __forceinline__ float4 clamp4(float4 m, float lo, float hi) {
    float4 r;
    r.x = clamp_elem(m.x, lo, hi);
    r.y = clamp_elem(m.y, lo, hi);
    r.z = clamp_elem(m.z, lo, hi);
    r.w = clamp_elem(m.w, lo, hi);
    return r;
}

// One block per (b,c) plane. grid = B*C = 8192, block = 128.
// Thread t handles float4 indices t + k*128, k=0..5, plus tail (t<16).
// 6 main + 6 dup (+2 tail) LDG.128 all front-batched; speculation on
// pred_j = c verified by ballot (reload path keeps general correctness).
__global__ void __launch_bounds__(128) edac_fused_kernel(
    const float4* __restrict__ main4,
    const float4* __restrict__ dup4,
    const float* __restrict__ min_vals,
    const float* __restrict__ max_vals,
    const int* __restrict__ vidx,
    float4* __restrict__ out4,
    int K)
{
    const int plane = blockIdx.x;
    const int c = plane & (CC - 1);
    const int b = plane >> 8;
    const int t = threadIdx.x;
    const int lane = t & 31;

    // Independent scalar loads first (K <= 64 in this problem).
    const int v0 = (lane < K)      ? __ldg(vidx + lane)      : (c ^ 1);
    const int v1 = (32 + lane < K) ? __ldg(vidx + 32 + lane) : (c ^ 1);
    const float lo = __ldg(min_vals + c);
    const float hi = __ldg(max_vals + c);

    const int mbase = plane * HW4 + t;        // < 2^23, int ok
    const bool tail = (t < HW4 - 6 * 128);    // t < 16

    // Front-batch ALL main loads.
    float4 m0 = __ldcs(main4 + mbase);
    float4 m1 = __ldcs(main4 + mbase + 128);
    float4 m2 = __ldcs(main4 + mbase + 256);
    float4 m3 = __ldcs(main4 + mbase + 384);
    float4 m4 = __ldcs(main4 + mbase + 512);
    float4 m5 = __ldcs(main4 + mbase + 640);
    float4 m6;
    if (tail) m6 = __ldcs(main4 + mbase + 768);

    // Speculative dup loads with pred_j = c (verified below).
    const int pred_j = (c < K) ? c : -1;
    float4 d0, d1, d2, d3, d4, d5, d6;
    if (pred_j >= 0) {
        const int pbase = (b * K + pred_j) * HW4 + t;
        d0 = __ldcs(dup4 + pbase);
        d1 = __ldcs(dup4 + pbase + 128);
        d2 = __ldcs(dup4 + pbase + 256);
        d3 = __ldcs(dup4 + pbase + 384);
        d4 = __ldcs(dup4 + pbase + 512);
        d5 = __ldcs(dup4 + pbase + 640);
        if (tail) d6 = __ldcs(dup4 + pbase + 768);
    }

    // j = last index with vidx[j] == c (mirrors .at[].set on duplicates).
    unsigned msk0 = __ballot_sync(0xffffffffu, v0 == c);
    unsigned msk1 = __ballot_sync(0xffffffffu, v1 == c);
    int j = -1;
    if (msk0) j = 31 - __clz(msk0);
    if (msk1) j = 63 - __clz(msk1);

    if (j >= 0) {
        if (j != pred_j) {   // misprediction: reload from the true j
            const int dbase = (b * K + j) * HW4 + t;
            d0 = __ldcs(dup4 + dbase);
            d1 = __ldcs(dup4 + dbase + 128);
            d2 = __ldcs(dup4 + dbase + 256);
            d3 = __ldcs(dup4 + dbase + 384);
            d4 = __ldcs(dup4 + dbase + 512);
            d5 = __ldcs(dup4 + dbase + 640);
            if (tail) d6 = __ldcs(dup4 + dbase + 768);
        }
        __stcs(out4 + mbase,       edac4(m0, d0, lo, hi));
        __stcs(out4 + mbase + 128, edac4(m1, d1, lo, hi));
        __stcs(out4 + mbase + 256, edac4(m2, d2, lo, hi));
        __stcs(out4 + mbase + 384, edac4(m3, d3, lo, hi));
        __stcs(out4 + mbase + 512, edac4(m4, d4, lo, hi));
        __stcs(out4 + mbase + 640, edac4(m5, d5, lo, hi));
        if (tail) __stcs(out4 + mbase + 768, edac4(m6, d6, lo, hi));
    } else {
        __stcs(out4 + mbase,       clamp4(m0, lo, hi));
        __stcs(out4 + mbase + 128, clamp4(m1, lo, hi));
        __stcs(out4 + mbase + 256, clamp4(m2, lo, hi));
        __stcs(out4 + mbase + 384, clamp4(m3, lo, hi));
        __stcs(out4 + mbase + 512, clamp4(m4, lo, hi));
        __stcs(out4 + mbase + 640, clamp4(m5, lo, hi));
        if (tail) __stcs(out4 + mbase + 768, clamp4(m6, lo, hi));
    }
}

extern "C" void kernel_launch(void* const* d_in, const int* in_sizes, int n_in,
                              void* d_out, int out_size) {
    const float* main_out = (const float*)d_in[0];
    const float* dup_out  = (const float*)d_in[1];
    const float* min_vals = (const float*)d_in[2];
    const float* max_vals = (const float*)d_in[3];
    const int*   vidx     = (const int*)d_in[4];
    float* out = (float*)d_out;

    int K = in_sizes[4];

    edac_fused_kernel<<<BB * CC, 128>>>(
        (const float4*)main_out, (const float4*)dup_out,
        min_vals, max_vals, vidx, (float4*)out, K);
}

// round 16
// speedup vs baseline: 1.0115x; 1.0115x over previous
#include <cuda_runtime.h>

// EDACLayer — FINAL kernel (best measured: 39.04us total / 29.79us kernel,
// 94-97% of 8 TB/s HBM spec on 231 MB compulsory traffic; floor = 28.9us).
//
// Shape (fixed): main (32,256,56,56) f32, dup (32,64,56,56) f32,
// min/max (256,), vidx (64,) i32, out (32,256,56,56) f32.
// lo <= 0 < hi by construction, inputs finite -> nan_to_num is a no-op
// for the final result (NaN/inf fail the range predicates either way).
//
// Structure (each element validated by a bench round):
//  - one block per half (b,c) plane, 128 threads (R6)
//  - all 8 LDG.128 front-batched per thread (R4 — dominant lever;
//    bounded both ways: fewer regressed 18% (R13), more was neutral (R15))
//  - dup loads speculated with pred_j = c, verified by ballot (R8: hides
//    the vidx-load latency; reload path keeps arbitrary-vidx correctness)
//  - __ldcs/__stcs streaming hints (R4)
// Rejected by measurement: two-stage loads (R3), persistent grid (R5),
// interleaved issue (R9), __stwt (R10), occupancy pin (R13),
// full-plane 13-wide batch (R15: neutral — LTS ceiling reached).
#define BB 32
#define CC 256
#define HWSZ (56 * 56)       // 3136
#define HW4 (HWSZ / 4)       // 784 float4 per plane
#define HALF4 (HW4 / 2)      // 392 = 3*128 + 8

__device__ __forceinline__ float edac_elem(float m, float d, float lo, float hi) {
    bool mv = (m >= lo) && (m <= hi);
    bool dv = (d >= lo) && (d <= hi);
    if (mv && dv) return fminf(m, d);   // m==d: fminf == m, same as ref
    if (dv) return d;
    return mv ? m : 0.0f;
}

__device__ __forceinline__ float clamp_elem(float m, float lo, float hi) {
    return ((m >= lo) && (m <= hi)) ? m : 0.0f;
}

__device__ __forceinline__ float4 edac4(float4 m, float4 d, float lo, float hi) {
    float4 r;
    r.x = edac_elem(m.x, d.x, lo, hi);
    r.y = edac_elem(m.y, d.y, lo, hi);
    r.z = edac_elem(m.z, d.z, lo, hi);
    r.w = edac_elem(m.w, d.w, lo, hi);
    return r;
}

__device__ __forceinline__ float4 clamp4(float4 m, float lo, float hi) {
    float4 r;
    r.x = clamp_elem(m.x, lo, hi);
    r.y = clamp_elem(m.y, lo, hi);
    r.z = clamp_elem(m.z, lo, hi);
    r.w = clamp_elem(m.w, lo, hi);
    return r;
}

__global__ void __launch_bounds__(128) edac_fused_kernel(
    const float4* __restrict__ main4,
    const float4* __restrict__ dup4,
    const float* __restrict__ min_vals,
    const float* __restrict__ max_vals,
    const int* __restrict__ vidx,
    float4* __restrict__ out4,
    int K)
{
    const int bid   = blockIdx.x;
    const int plane = bid >> 1;
    const int half  = bid & 1;
    const int c = plane & (CC - 1);
    const int b = plane >> 8;
    const int t = threadIdx.x;
    const int lane = t & 31;

    // Independent scalar loads first (K <= 64 in this problem).
    const int v0 = (lane < K)      ? __ldg(vidx + lane)      : (c ^ 1);
    const int v1 = (32 + lane < K) ? __ldg(vidx + 32 + lane) : (c ^ 1);
    const float lo = __ldg(min_vals + c);
    const float hi = __ldg(max_vals + c);

    const int mbase = plane * HW4 + half * HALF4 + t;   // < 2^23, int ok
    const bool tail = (t < HALF4 - 3 * 128);            // t < 8

    // Front-batch the main loads (independent of everything above).
    float4 m0 = __ldcs(main4 + mbase);
    float4 m1 = __ldcs(main4 + mbase + 128);
    float4 m2 = __ldcs(main4 + mbase + 256);
    float4 m3;
    if (tail) m3 = __ldcs(main4 + mbase + 384);

    // Speculative dup loads with pred_j = c (verified below).
    const int pred_j = (c < K) ? c : -1;
    float4 d0, d1, d2, d3;
    if (pred_j >= 0) {
        const int pbase = (b * K + pred_j) * HW4 + half * HALF4 + t;
        d0 = __ldcs(dup4 + pbase);
        d1 = __ldcs(dup4 + pbase + 128);
        d2 = __ldcs(dup4 + pbase + 256);
        if (tail) d3 = __ldcs(dup4 + pbase + 384);
    }

    // j = last index with vidx[j] == c (mirrors .at[].set on duplicates).
    unsigned msk0 = __ballot_sync(0xffffffffu, v0 == c);
    unsigned msk1 = __ballot_sync(0xffffffffu, v1 == c);
    int j = -1;
    if (msk0) j = 31 - __clz(msk0);
    if (msk1) j = 63 - __clz(msk1);

    if (j >= 0) {
        if (j != pred_j) {   // misprediction: reload from the true j
            const int dbase = (b * K + j) * HW4 + half * HALF4 + t;
            d0 = __ldcs(dup4 + dbase);
            d1 = __ldcs(dup4 + dbase + 128);
            d2 = __ldcs(dup4 + dbase + 256);
            if (tail) d3 = __ldcs(dup4 + dbase + 384);
        }
        __stcs(out4 + mbase,       edac4(m0, d0, lo, hi));
        __stcs(out4 + mbase + 128, edac4(m1, d1, lo, hi));
        __stcs(out4 + mbase + 256, edac4(m2, d2, lo, hi));
        if (tail) __stcs(out4 + mbase + 384, edac4(m3, d3, lo, hi));
    } else {
        __stcs(out4 + mbase,       clamp4(m0, lo, hi));
        __stcs(out4 + mbase + 128, clamp4(m1, lo, hi));
        __stcs(out4 + mbase + 256, clamp4(m2, lo, hi));
        if (tail) __stcs(out4 + mbase + 384, clamp4(m3, lo, hi));
    }
}

extern "C" void kernel_launch(void* const* d_in, const int* in_sizes, int n_in,
                              void* d_out, int out_size) {
    const float* main_out = (const float*)d_in[0];
    const float* dup_out  = (const float*)d_in[1];
    const float* min_vals = (const float*)d_in[2];
    const float* max_vals = (const float*)d_in[3];
    const int*   vidx     = (const int*)d_in[4];
    float* out = (float*)d_out;

    int K = in_sizes[4];

    edac_fused_kernel<<<2 * BB * CC, 128>>>(
        (const float4*)main_out, (const float4*)dup_out,
        min_vals, max_vals, vidx, (float4*)out, K);
}